// round 14
// baseline (speedup 1.0000x reference)
#include <cuda_runtime.h>
#include <cuda_bf16.h>
#include <cstdint>

#define N_NODES 50000
#define N_EDGES 640000
#define D 128

#define SCAN_TILE 1024
#define SCAN_NBLK ((N_NODES + SCAN_TILE - 1) / SCAN_TILE)   // 49

typedef unsigned long long ULL;

// ---------------- device scratch (no allocations allowed) ----------------
// INVARIANT: g_count and g_scanstate are ZERO at entry to every kernel_launch
// call (BSS-zero first call; scan re-zeroes g_count, scatter re-zeroes
// g_scanstate on every replay).
__device__ int                g_is64;
__device__ int                g_count[N_NODES];
__device__ int                g_offsets[N_NODES + 1];
__device__ int                g_cursor[N_NODES];
__device__ unsigned int       g_scanstate[SCAN_NBLK];
__device__ ULL                g_edge_sorted[N_EDGES];   // (w_bits<<32) | src

__device__ __forceinline__ int edge_idx(const void* p, int i, int is64) {
    if (is64) return (int)__ldg(((const long long*)p) + i);
    return __ldg(((const int*)p) + i);
}

// ---------------- tiny detect: int32 vs int64 indices ----------------
__global__ void detect_kernel(const void* src, const void* dst) {
    if (threadIdx.x == 0) {
        g_offsets[N_NODES] = N_EDGES;
        const long long* s = (const long long*)src;
        const long long* d = (const long long*)dst;
        bool ok = true;
        for (int j = 0; j < 8; j++) {
            long long a = s[j], b = d[j];
            if (a < 0 || a >= N_NODES || b < 0 || b >= N_NODES) { ok = false; break; }
        }
        g_is64 = ok ? 1 : 0;
    }
}

// ---------------- count: 1 edge/thread ----------------
__global__ void count_kernel(const void* dst) {
    int e = blockIdx.x * blockDim.x + threadIdx.x;
    if (e >= N_EDGES) return;
    int is64 = g_is64;
    atomicAdd(&g_count[edge_idx(dst, e, is64)], 1);
}

// ---------------- single-pass exclusive scan, decoupled lookback ----------------
__global__ void scan_lookback_kernel() {
    __shared__ int warpsums[8];
    __shared__ int blockexcl;
    int t    = threadIdx.x;
    int lane = t & 31;
    int wrp  = t >> 5;
    int b    = blockIdx.x;
    int base = b * SCAN_TILE + t * 4;

    int c[4];
    int lsum = 0;
    #pragma unroll
    for (int i = 0; i < 4; i++) {
        int idx = base + i;
        c[i] = (idx < N_NODES) ? g_count[idx] : 0;
        if (idx < N_NODES) g_count[idx] = 0;       // re-establish zero invariant
        lsum += c[i];
    }
    int incl = lsum;
    #pragma unroll
    for (int o = 1; o < 32; o <<= 1) {
        int v = __shfl_up_sync(0xFFFFFFFF, incl, o);
        if (lane >= o) incl += v;
    }
    if (lane == 31) warpsums[wrp] = incl;
    __syncthreads();

    if (t == 0) {
        int tot = 0;
        #pragma unroll
        for (int wv = 0; wv < 8; wv++) tot += warpsums[wv];
        atomicExch(&g_scanstate[b], 0x80000000u | (unsigned)tot);
    }
    if (wrp == 0) {
        int psum = 0;
        for (int p = lane; p < b; p += 32) {
            unsigned v;
            do { v = atomicOr(&g_scanstate[p], 0u); } while (!(v & 0x80000000u));
            psum += (int)(v & 0x7FFFFFFFu);
        }
        #pragma unroll
        for (int o = 16; o > 0; o >>= 1) psum += __shfl_down_sync(0xFFFFFFFF, psum, o);
        if (lane == 0) blockexcl = psum;
    }
    __syncthreads();

    int wbase = 0;
    #pragma unroll
    for (int wv = 0; wv < 8; wv++) {
        int v = warpsums[wv];
        if (wv < wrp) wbase += v;
    }
    int run = blockexcl + wbase + (incl - lsum);
    #pragma unroll
    for (int i = 0; i < 4; i++) {
        int idx = base + i;
        if (idx < N_NODES) {
            g_offsets[idx] = run;
            g_cursor[idx]  = run;
            run += c[i];
        }
    }
}

// ---------------- scatter: 1 edge/thread; also zero g_scanstate ----------------
__global__ void scatter_kernel(const void* src, const void* dst, const float* __restrict__ w) {
    int e = blockIdx.x * blockDim.x + threadIdx.x;
    if (e < SCAN_NBLK) g_scanstate[e] = 0u;        // re-establish zero invariant
    if (e >= N_EDGES) return;
    int is64 = g_is64;
    int d = edge_idx(dst, e, is64);
    int s = edge_idx(src, e, is64);
    float wv = __ldg(w + e);
    int pos = atomicAdd(&g_cursor[d], 1);
    g_edge_sorted[pos] = ((ULL)__float_as_uint(wv) << 32) | (unsigned)s;
}

// ================= FUSED aggregate + bi-interaction GEMM =====================
// Per M=32 node tile: 16 warps aggregate 2 nodes each (CSR gather -> hn to
// gmem, (h+hn)/(h*hn) bf16 hi/lo straight into smem), then mma.sync phase.
// Double-buffered A tiles overlap aggregate(t+1) gathers with MMA(t) issue.

#define PAD 136
#define WTILE_B (128 * PAD * 2)          // 34816
#define ATILE_B (32 * PAD * 2)           // 8704
#define SW1_HI 0
#define SW1_LO (SW1_HI + WTILE_B)
#define SW2_HI (SW1_LO + WTILE_B)
#define SW2_LO (SW2_HI + WTILE_B)
#define A_BASE (SW2_LO + WTILE_B)        // 139264
// A buffer: [buf p][branch br][hi/lo l]
#define A_OFF(p, br, l) (A_BASE + (((p) * 2 + (br)) * 2 + (l)) * ATILE_B)
#define SM_TOTAL (A_BASE + 8 * ATILE_B)  // 208896 B

#define MTILE 32
#define N_TILES ((N_NODES + MTILE - 1) / MTILE)   // 1563

__device__ __forceinline__ float lrelu(float x) { return x > 0.f ? x : 0.01f * x; }
__device__ __forceinline__ unsigned pack2(float a, float b) {
    unsigned short ua = __bfloat16_as_ushort(__float2bfloat16_rn(a));
    unsigned short ub = __bfloat16_as_ushort(__float2bfloat16_rn(b));
    return (unsigned)ua | ((unsigned)ub << 16);
}
__device__ __forceinline__ float bflo(float x) {
    return x - __bfloat162float(__float2bfloat16_rn(x));
}
__device__ __forceinline__ uint32_t smem_u32(const void* p) {
    uint32_t a;
    asm("{ .reg .u64 t; cvta.to.shared.u64 t, %1; cvt.u32.u64 %0, t; }" : "=r"(a) : "l"(p));
    return a;
}
__device__ __forceinline__ void mma16816(float* c, const unsigned* a, const unsigned* b) {
    asm volatile(
        "mma.sync.aligned.m16n8k16.row.col.f32.bf16.bf16.f32 "
        "{%0,%1,%2,%3}, {%4,%5,%6,%7}, {%8,%9}, {%0,%1,%2,%3};"
        : "+f"(c[0]), "+f"(c[1]), "+f"(c[2]), "+f"(c[3])
        : "r"(a[0]), "r"(a[1]), "r"(a[2]), "r"(a[3]), "r"(b[0]), "r"(b[1]));
}
__device__ __forceinline__ void ldsm4(unsigned* r, uint32_t addr) {
    asm volatile("ldmatrix.sync.aligned.m8n8.x4.shared.b16 {%0,%1,%2,%3}, [%4];"
                 : "=r"(r[0]), "=r"(r[1]), "=r"(r[2]), "=r"(r[3]) : "r"(addr));
}

__device__ __forceinline__ void st_pairs(char* smem, int base, int r, int k,
                                         float x0, float x1, float x2, float x3,
                                         int lo_base) {
    unsigned* hp = (unsigned*)(smem + base + r * (PAD * 2) + k * 2);
    hp[0] = pack2(x0, x1);
    hp[1] = pack2(x2, x3);
    unsigned* lp = (unsigned*)(smem + lo_base + r * (PAD * 2) + k * 2);
    lp[0] = pack2(bflo(x0), bflo(x1));
    lp[1] = pack2(bflo(x2), bflo(x3));
}

__device__ __forceinline__ void stA(char* smem, int hbase, int lbase, int r, int k, float4 v) {
    unsigned u0 = __float_as_uint(v.x), u1 = __float_as_uint(v.y);
    unsigned u2 = __float_as_uint(v.z), u3 = __float_as_uint(v.w);
    unsigned h0, h1;
    asm("prmt.b32 %0, %1, %2, 0x7632;" : "=r"(h0) : "r"(u0), "r"(u1));
    asm("prmt.b32 %0, %1, %2, 0x7632;" : "=r"(h1) : "r"(u2), "r"(u3));
    float l0 = v.x - __uint_as_float(u0 & 0xffff0000u);
    float l1 = v.y - __uint_as_float(u1 & 0xffff0000u);
    float l2 = v.z - __uint_as_float(u2 & 0xffff0000u);
    float l3 = v.w - __uint_as_float(u3 & 0xffff0000u);
    unsigned p0, p1;
    asm("cvt.rn.bf16x2.f32 %0, %1, %2;" : "=r"(p0) : "f"(l1), "f"(l0));
    asm("cvt.rn.bf16x2.f32 %0, %1, %2;" : "=r"(p1) : "f"(l3), "f"(l2));
    *(uint2*)(smem + hbase + r * (PAD * 2) + k * 2) = make_uint2(h0, h1);
    *(uint2*)(smem + lbase + r * (PAD * 2) + k * 2) = make_uint2(p0, p1);
}

__global__ void __launch_bounds__(512, 1)
fused_agg_gemm_kernel(const float* __restrict__ nfeat,
                      const float* __restrict__ W1,
                      const float* __restrict__ W2,
                      float* __restrict__ hn,
                      float* __restrict__ out) {
    extern __shared__ char smem[];
    uint32_t sb = smem_u32(smem);
    int tid  = threadIdx.x;
    int wid  = tid >> 5;          // 0..15
    int lane = tid & 31;
    int g8   = lane >> 2;
    int t4   = lane & 3;

    int warp_r = wid >> 3;        // 0..1 -> row base warp_r*16
    int warp_c = wid & 7;         // 0..7 -> col base warp_c*16

    // ldmatrix per-lane offsets (bytes)
    int a_off = (warp_r * 16 + ((lane >> 3) & 1) * 8 + (lane & 7)) * (PAD * 2)
              + (lane >> 4) * 16;
    int b_off = (warp_c * 16 + (lane >> 4) * 8 + (lane & 7)) * (PAD * 2)
              + ((lane >> 3) & 1) * 16;

    // ---- stage weight splits once ----
    {
        int r  = tid >> 2;            // 0..127
        int kc = (tid & 3) * 32;
        const float4* w1p = (const float4*)(W1 + (size_t)r * D + kc);
        const float4* w2p = (const float4*)(W2 + (size_t)r * D + kc);
        #pragma unroll
        for (int i = 0; i < 8; i++) {
            float4 a = __ldg(w1p + i);
            float4 b = __ldg(w2p + i);
            int k = kc + i * 4;
            st_pairs(smem, SW1_HI, r, k, a.x, a.y, a.z, a.w, SW1_LO);
            st_pairs(smem, SW2_HI, r, k, b.x, b.y, b.z, b.w, SW2_LO);
        }
    }

    // ---- aggregate + stage one tile into buffer p ----
    auto stage_tile = [&](int t, int p) {
        int n0 = t * MTILE;
        #pragma unroll
        for (int q = 0; q < 2; q++) {
            int node = n0 + wid * 2 + q;
            float4 av = make_float4(0.f, 0.f, 0.f, 0.f);
            float4 mv = av;
            if (node < N_NODES) {
                int beg = g_offsets[node];
                int end = g_offsets[node + 1];
                float4 acc = make_float4(0.f, 0.f, 0.f, 0.f);
                int e = beg;
                for (; e + 3 < end; e += 4) {
                    ULL p0 = __ldg(&g_edge_sorted[e]);
                    ULL p1 = __ldg(&g_edge_sorted[e + 1]);
                    ULL p2 = __ldg(&g_edge_sorted[e + 2]);
                    ULL p3 = __ldg(&g_edge_sorted[e + 3]);
                    float4 v0 = __ldg(((const float4*)(nfeat + (size_t)(unsigned)(p0 & 0xFFFFFFFFu) * D)) + lane);
                    float4 v1 = __ldg(((const float4*)(nfeat + (size_t)(unsigned)(p1 & 0xFFFFFFFFu) * D)) + lane);
                    float4 v2 = __ldg(((const float4*)(nfeat + (size_t)(unsigned)(p2 & 0xFFFFFFFFu) * D)) + lane);
                    float4 v3 = __ldg(((const float4*)(nfeat + (size_t)(unsigned)(p3 & 0xFFFFFFFFu) * D)) + lane);
                    float w0 = __uint_as_float((unsigned)(p0 >> 32));
                    float w1 = __uint_as_float((unsigned)(p1 >> 32));
                    float w2 = __uint_as_float((unsigned)(p2 >> 32));
                    float w3 = __uint_as_float((unsigned)(p3 >> 32));
                    acc.x += w0 * v0.x; acc.y += w0 * v0.y; acc.z += w0 * v0.z; acc.w += w0 * v0.w;
                    acc.x += w1 * v1.x; acc.y += w1 * v1.y; acc.z += w1 * v1.z; acc.w += w1 * v1.w;
                    acc.x += w2 * v2.x; acc.y += w2 * v2.y; acc.z += w2 * v2.z; acc.w += w2 * v2.w;
                    acc.x += w3 * v3.x; acc.y += w3 * v3.y; acc.z += w3 * v3.z; acc.w += w3 * v3.w;
                }
                for (; e < end; e++) {
                    ULL p0 = __ldg(&g_edge_sorted[e]);
                    float4 v0 = __ldg(((const float4*)(nfeat + (size_t)(unsigned)(p0 & 0xFFFFFFFFu) * D)) + lane);
                    float w0 = __uint_as_float((unsigned)(p0 >> 32));
                    acc.x += w0 * v0.x; acc.y += w0 * v0.y; acc.z += w0 * v0.z; acc.w += w0 * v0.w;
                }
                // write h_neighbor (output 1)
                ((float4*)(hn + (size_t)node * D))[lane] = acc;
                float4 hv = __ldg(((const float4*)(nfeat + (size_t)node * D)) + lane);
                av = make_float4(hv.x + acc.x, hv.y + acc.y, hv.z + acc.z, hv.w + acc.w);
                mv = make_float4(hv.x * acc.x, hv.y * acc.y, hv.z * acc.z, hv.w * acc.w);
            }
            int r = wid * 2 + q;
            stA(smem, A_OFF(p, 0, 0), A_OFF(p, 0, 1), r, lane * 4, av);
            stA(smem, A_OFF(p, 1, 0), A_OFF(p, 1, 1), r, lane * 4, mv);
        }
    };

    int tile = blockIdx.x;
    int p = 0;
    if (tile < N_TILES) stage_tile(tile, 0);
    __syncthreads();   // weights + first tile staged

    for (; tile < N_TILES; tile += gridDim.x) {
        // ---- MMA phase on buffer p ----
        float acc[2][2][4];
        #pragma unroll
        for (int b = 0; b < 2; b++)
            #pragma unroll
            for (int ni = 0; ni < 2; ni++)
                #pragma unroll
                for (int f = 0; f < 4; f++) acc[b][ni][f] = 0.f;

        #pragma unroll
        for (int branch = 0; branch < 2; branch++) {
            uint32_t ahi = sb + A_OFF(p, branch, 0);
            uint32_t alo = sb + A_OFF(p, branch, 1);
            uint32_t bhi = sb + (branch ? SW2_HI : SW1_HI);
            uint32_t blo = sb + (branch ? SW2_LO : SW1_LO);

            #pragma unroll
            for (int kk = 0; kk < 8; kk++) {
                int kb2 = kk * 32;
                unsigned afr[4];
                ldsm4(afr, ahi + a_off + kb2);
                unsigned bh[4], bl[4];
                ldsm4(bh, bhi + b_off + kb2);
                ldsm4(bl, blo + b_off + kb2);
                #pragma unroll
                for (int ni = 0; ni < 2; ni++) {
                    mma16816(acc[branch][ni], afr, bh + ni * 2);
                    mma16816(acc[branch][ni], afr, bl + ni * 2);
                }
            }
            #pragma unroll
            for (int kk = 0; kk < 8; kk++) {
                int kb2 = kk * 32;
                unsigned afr[4];
                ldsm4(afr, alo + a_off + kb2);
                unsigned bh[4];
                ldsm4(bh, bhi + b_off + kb2);
                #pragma unroll
                for (int ni = 0; ni < 2; ni++)
                    mma16816(acc[branch][ni], afr, bh + ni * 2);
            }
        }

        // ---- epilogue ----
        {
            int n0 = tile * MTILE;
            int r_lo = n0 + warp_r * 16 + g8;
            int r_hi = r_lo + 8;
            #pragma unroll
            for (int ni = 0; ni < 2; ni++) {
                int c0 = warp_c * 16 + ni * 8 + t4 * 2;
                if (r_lo < N_NODES) {
                    float2 o;
                    o.x = lrelu(acc[0][ni][0]) + lrelu(acc[1][ni][0]);
                    o.y = lrelu(acc[0][ni][1]) + lrelu(acc[1][ni][1]);
                    *(float2*)(out + (size_t)r_lo * D + c0) = o;
                }
                if (r_hi < N_NODES) {
                    float2 o;
                    o.x = lrelu(acc[0][ni][2]) + lrelu(acc[1][ni][2]);
                    o.y = lrelu(acc[0][ni][3]) + lrelu(acc[1][ni][3]);
                    *(float2*)(out + (size_t)r_hi * D + c0) = o;
                }
            }
        }

        // ---- overlap: aggregate next tile into the other buffer ----
        int nxt = tile + gridDim.x;
        if (nxt < N_TILES) stage_tile(nxt, p ^ 1);
        __syncthreads();   // buf p^1 complete; buf p free for the tile after
        p ^= 1;
    }
}

// ---------------- launch ----------------
extern "C" void kernel_launch(void* const* d_in, const int* in_sizes, int n_in,
                              void* d_out, int out_size) {
    const float* nfeat = (const float*)d_in[0];
    const float* w     = (const float*)d_in[1];
    const float* W1    = (const float*)d_in[2];
    const float* W2    = (const float*)d_in[3];
    const void*  src   = d_in[4];
    const void*  dst   = d_in[5];

    float* outbuf = (float*)d_out;
    float* hn     = outbuf;                           // h_neighbor
    float* out2   = outbuf + (size_t)N_NODES * D;     // out

    detect_kernel<<<1, 32>>>(src, dst);
    count_kernel<<<(N_EDGES + 255) / 256, 256>>>(dst);
    scan_lookback_kernel<<<SCAN_NBLK, 256>>>();
    scatter_kernel<<<(N_EDGES + 255) / 256, 256>>>(src, dst, w);

    cudaFuncSetAttribute(fused_agg_gemm_kernel,
                         cudaFuncAttributeMaxDynamicSharedMemorySize, SM_TOTAL);
    fused_agg_gemm_kernel<<<148, 512, SM_TOTAL>>>(nfeat, W1, W2, hn, out2);
}

// round 15
// speedup vs baseline: 1.2774x; 1.2774x over previous
#include <cuda_runtime.h>
#include <cuda_bf16.h>
#include <cstdint>

#define N_NODES 50000
#define N_EDGES 640000
#define D 128

#define SCAN_TILE 1024
#define SCAN_NBLK ((N_NODES + SCAN_TILE - 1) / SCAN_TILE)   // 49

typedef unsigned long long ULL;

// ---------------- device scratch (no allocations allowed) ----------------
// INVARIANT: g_count, g_scanstate, g_tile_counter are ZERO at entry to every
// kernel_launch call (BSS-zero first call; scan re-zeroes g_count, scatter
// re-zeroes g_scanstate and g_tile_counter on every replay).
__device__ int                g_count[N_NODES];
__device__ int                g_offsets[N_NODES + 1];
__device__ int                g_cursor[N_NODES];
__device__ unsigned int       g_scanstate[SCAN_NBLK];
__device__ int                g_tile_counter;
__device__ ULL                g_edge_sorted[N_EDGES];   // (w_bits<<32) | src

__device__ __forceinline__ int edge_idx(const void* p, int i, int is64) {
    if (is64) return (int)__ldg(((const long long*)p) + i);
    return __ldg(((const int*)p) + i);
}

// Per-block dtype detection: int32 data read as int64 pairs two words ->
// out-of-range values -> is64=0. Deterministic, ~8 cached loads per block.
__device__ __forceinline__ int detect_is64_block(const void* dst, int* s_is64) {
    if (threadIdx.x == 0) {
        const long long* d = (const long long*)dst;
        bool ok = true;
        #pragma unroll
        for (int j = 0; j < 8; j++) {
            long long b = d[j];
            if (b < 0 || b >= N_NODES) { ok = false; break; }
        }
        *s_is64 = ok ? 1 : 0;
    }
    __syncthreads();
    return *s_is64;
}

// ---------------- count: 1 edge/thread ----------------
__global__ void count_kernel(const void* dst) {
    __shared__ int s_is64;
    int is64 = detect_is64_block(dst, &s_is64);
    int e = blockIdx.x * blockDim.x + threadIdx.x;
    if (e >= N_EDGES) return;
    atomicAdd(&g_count[edge_idx(dst, e, is64)], 1);
}

// ---------------- single-pass exclusive scan, decoupled lookback ----------------
__global__ void scan_lookback_kernel() {
    __shared__ int warpsums[8];
    __shared__ int blockexcl;
    int t    = threadIdx.x;
    int lane = t & 31;
    int wrp  = t >> 5;
    int b    = blockIdx.x;
    int base = b * SCAN_TILE + t * 4;

    if (b == 0 && t == 0) g_offsets[N_NODES] = N_EDGES;

    int c[4];
    int lsum = 0;
    #pragma unroll
    for (int i = 0; i < 4; i++) {
        int idx = base + i;
        c[i] = (idx < N_NODES) ? g_count[idx] : 0;
        if (idx < N_NODES) g_count[idx] = 0;       // re-establish zero invariant
        lsum += c[i];
    }
    int incl = lsum;
    #pragma unroll
    for (int o = 1; o < 32; o <<= 1) {
        int v = __shfl_up_sync(0xFFFFFFFF, incl, o);
        if (lane >= o) incl += v;
    }
    if (lane == 31) warpsums[wrp] = incl;
    __syncthreads();

    if (t == 0) {
        int tot = 0;
        #pragma unroll
        for (int wv = 0; wv < 8; wv++) tot += warpsums[wv];
        atomicExch(&g_scanstate[b], 0x80000000u | (unsigned)tot);
    }
    if (wrp == 0) {
        int psum = 0;
        for (int p = lane; p < b; p += 32) {
            unsigned v;
            do { v = atomicOr(&g_scanstate[p], 0u); } while (!(v & 0x80000000u));
            psum += (int)(v & 0x7FFFFFFFu);
        }
        #pragma unroll
        for (int o = 16; o > 0; o >>= 1) psum += __shfl_down_sync(0xFFFFFFFF, psum, o);
        if (lane == 0) blockexcl = psum;
    }
    __syncthreads();

    int wbase = 0;
    #pragma unroll
    for (int wv = 0; wv < 8; wv++) {
        int v = warpsums[wv];
        if (wv < wrp) wbase += v;
    }
    int run = blockexcl + wbase + (incl - lsum);
    #pragma unroll
    for (int i = 0; i < 4; i++) {
        int idx = base + i;
        if (idx < N_NODES) {
            g_offsets[idx] = run;
            g_cursor[idx]  = run;
            run += c[i];
        }
    }
}

// ---------------- scatter: 1 edge/thread; re-zero scan state + tile counter ----
__global__ void scatter_kernel(const void* src, const void* dst, const float* __restrict__ w) {
    __shared__ int s_is64;
    int is64 = detect_is64_block(dst, &s_is64);
    int e = blockIdx.x * blockDim.x + threadIdx.x;
    if (e < SCAN_NBLK) g_scanstate[e] = 0u;        // re-establish zero invariant
    if (e == SCAN_NBLK) g_tile_counter = 0;        // reset GEMM work queue
    if (e >= N_EDGES) return;
    int d = edge_idx(dst, e, is64);
    int s = edge_idx(src, e, is64);
    float wv = __ldg(w + e);
    int pos = atomicAdd(&g_cursor[d], 1);
    g_edge_sorted[pos] = ((ULL)__float_as_uint(wv) << 32) | (unsigned)s;
}

// ---------------- per-node aggregation: one warp per node ----------------
__global__ void aggregate_kernel(const float* __restrict__ nfeat, float* __restrict__ hn) {
    int gwarp = (blockIdx.x * blockDim.x + threadIdx.x) >> 5;
    int lane  = threadIdx.x & 31;
    if (gwarp >= N_NODES) return;
    int beg = g_offsets[gwarp];
    int end = g_offsets[gwarp + 1];
    float4 acc = make_float4(0.f, 0.f, 0.f, 0.f);
    int e = beg;
    for (; e + 3 < end; e += 4) {
        ULL p0 = __ldg(&g_edge_sorted[e]);
        ULL p1 = __ldg(&g_edge_sorted[e + 1]);
        ULL p2 = __ldg(&g_edge_sorted[e + 2]);
        ULL p3 = __ldg(&g_edge_sorted[e + 3]);
        float4 v0 = __ldg(((const float4*)(nfeat + (size_t)(unsigned)(p0 & 0xFFFFFFFFu) * D)) + lane);
        float4 v1 = __ldg(((const float4*)(nfeat + (size_t)(unsigned)(p1 & 0xFFFFFFFFu) * D)) + lane);
        float4 v2 = __ldg(((const float4*)(nfeat + (size_t)(unsigned)(p2 & 0xFFFFFFFFu) * D)) + lane);
        float4 v3 = __ldg(((const float4*)(nfeat + (size_t)(unsigned)(p3 & 0xFFFFFFFFu) * D)) + lane);
        float w0 = __uint_as_float((unsigned)(p0 >> 32));
        float w1 = __uint_as_float((unsigned)(p1 >> 32));
        float w2 = __uint_as_float((unsigned)(p2 >> 32));
        float w3 = __uint_as_float((unsigned)(p3 >> 32));
        acc.x += w0 * v0.x; acc.y += w0 * v0.y; acc.z += w0 * v0.z; acc.w += w0 * v0.w;
        acc.x += w1 * v1.x; acc.y += w1 * v1.y; acc.z += w1 * v1.z; acc.w += w1 * v1.w;
        acc.x += w2 * v2.x; acc.y += w2 * v2.y; acc.z += w2 * v2.z; acc.w += w2 * v2.w;
        acc.x += w3 * v3.x; acc.y += w3 * v3.y; acc.z += w3 * v3.z; acc.w += w3 * v3.w;
    }
    for (; e < end; e++) {
        ULL p0 = __ldg(&g_edge_sorted[e]);
        float4 v0 = __ldg(((const float4*)(nfeat + (size_t)(unsigned)(p0 & 0xFFFFFFFFu) * D)) + lane);
        float w0 = __uint_as_float((unsigned)(p0 >> 32));
        acc.x += w0 * v0.x; acc.y += w0 * v0.y; acc.z += w0 * v0.z; acc.w += w0 * v0.w;
    }
    ((float4*)(hn + (size_t)gwarp * D))[lane] = acc;
}

// ================= mma.sync bi-interaction GEMM, M=64 tiles, 512 threads =====
// Work-stealing tile queue for last-wave balance; otherwise identical to the
// 108.5us configuration (16 warps, warp tile 32x16, 3-product bf16 split).

#define PAD 136
#define WTILE_B (128 * PAD * 2)
#define ATILE_B (64 * PAD * 2)
#define SW1_HI 0
#define SW1_LO (SW1_HI + WTILE_B)
#define SW2_HI (SW1_LO + WTILE_B)
#define SW2_LO (SW2_HI + WTILE_B)
#define SADD_HI (SW2_LO + WTILE_B)
#define SADD_LO (SADD_HI + ATILE_B)
#define SMUL_HI (SADD_LO + ATILE_B)
#define SMUL_LO (SMUL_HI + ATILE_B)
#define SM_TOTAL (SMUL_LO + ATILE_B)     // 208896 B

__device__ __forceinline__ float lrelu(float x) { return x > 0.f ? x : 0.01f * x; }
__device__ __forceinline__ unsigned pack2(float a, float b) {
    unsigned short ua = __bfloat16_as_ushort(__float2bfloat16_rn(a));
    unsigned short ub = __bfloat16_as_ushort(__float2bfloat16_rn(b));
    return (unsigned)ua | ((unsigned)ub << 16);
}
__device__ __forceinline__ float bflo(float x) {
    return x - __bfloat162float(__float2bfloat16_rn(x));
}
__device__ __forceinline__ uint32_t smem_u32(const void* p) {
    uint32_t a;
    asm("{ .reg .u64 t; cvta.to.shared.u64 t, %1; cvt.u32.u64 %0, t; }" : "=r"(a) : "l"(p));
    return a;
}
__device__ __forceinline__ void mma16816(float* c, const unsigned* a, const unsigned* b) {
    asm volatile(
        "mma.sync.aligned.m16n8k16.row.col.f32.bf16.bf16.f32 "
        "{%0,%1,%2,%3}, {%4,%5,%6,%7}, {%8,%9}, {%0,%1,%2,%3};"
        : "+f"(c[0]), "+f"(c[1]), "+f"(c[2]), "+f"(c[3])
        : "r"(a[0]), "r"(a[1]), "r"(a[2]), "r"(a[3]), "r"(b[0]), "r"(b[1]));
}
__device__ __forceinline__ void ldsm4(unsigned* r, uint32_t addr) {
    asm volatile("ldmatrix.sync.aligned.m8n8.x4.shared.b16 {%0,%1,%2,%3}, [%4];"
                 : "=r"(r[0]), "=r"(r[1]), "=r"(r[2]), "=r"(r[3]) : "r"(addr));
}

__device__ __forceinline__ void st_pairs(char* smem, int base, int r, int k,
                                         float x0, float x1, float x2, float x3,
                                         int lo_base) {
    unsigned* hp = (unsigned*)(smem + base + r * (PAD * 2) + k * 2);
    hp[0] = pack2(x0, x1);
    hp[1] = pack2(x2, x3);
    unsigned* lp = (unsigned*)(smem + lo_base + r * (PAD * 2) + k * 2);
    lp[0] = pack2(bflo(x0), bflo(x1));
    lp[1] = pack2(bflo(x2), bflo(x3));
}

__device__ __forceinline__ void stA(char* smem, int hbase, int lbase, int r, int k, float4 v) {
    unsigned u0 = __float_as_uint(v.x), u1 = __float_as_uint(v.y);
    unsigned u2 = __float_as_uint(v.z), u3 = __float_as_uint(v.w);
    unsigned h0, h1;
    asm("prmt.b32 %0, %1, %2, 0x7632;" : "=r"(h0) : "r"(u0), "r"(u1));
    asm("prmt.b32 %0, %1, %2, 0x7632;" : "=r"(h1) : "r"(u2), "r"(u3));
    float l0 = v.x - __uint_as_float(u0 & 0xffff0000u);
    float l1 = v.y - __uint_as_float(u1 & 0xffff0000u);
    float l2 = v.z - __uint_as_float(u2 & 0xffff0000u);
    float l3 = v.w - __uint_as_float(u3 & 0xffff0000u);
    unsigned p0, p1;
    asm("cvt.rn.bf16x2.f32 %0, %1, %2;" : "=r"(p0) : "f"(l1), "f"(l0));
    asm("cvt.rn.bf16x2.f32 %0, %1, %2;" : "=r"(p1) : "f"(l3), "f"(l2));
    *(uint2*)(smem + hbase + r * (PAD * 2) + k * 2) = make_uint2(h0, h1);
    *(uint2*)(smem + lbase + r * (PAD * 2) + k * 2) = make_uint2(p0, p1);
}

__global__ void __launch_bounds__(512, 1)
mma_gemm_kernel(const float* __restrict__ nfeat,
                const float* __restrict__ W1,
                const float* __restrict__ W2,
                const float* __restrict__ hn,
                float* __restrict__ out) {
    extern __shared__ char smem[];
    __shared__ int s_tile;
    uint32_t sb = smem_u32(smem);
    int tid  = threadIdx.x;
    int wid  = tid >> 5;          // 0..15
    int lane = tid & 31;
    int g8   = lane >> 2;
    int t4   = lane & 3;

    int warp_r = wid >> 3;        // 0..1  -> row base warp_r*32
    int warp_c = wid & 7;         // 0..7  -> col base warp_c*16

    int a_off = (warp_r * 32 + ((lane >> 3) & 1) * 8 + (lane & 7)) * (PAD * 2)
              + (lane >> 4) * 16;
    int b_off = (warp_c * 16 + (lane >> 4) * 8 + (lane & 7)) * (PAD * 2)
              + ((lane >> 3) & 1) * 16;

    // ---- stage weight splits once; fetch first tile ----
    {
        int r  = tid >> 2;            // 0..127
        int kc = (tid & 3) * 32;
        const float4* w1p = (const float4*)(W1 + (size_t)r * D + kc);
        const float4* w2p = (const float4*)(W2 + (size_t)r * D + kc);
        #pragma unroll
        for (int i = 0; i < 8; i++) {
            float4 a = __ldg(w1p + i);
            float4 b = __ldg(w2p + i);
            int k = kc + i * 4;
            st_pairs(smem, SW1_HI, r, k, a.x, a.y, a.z, a.w, SW1_LO);
            st_pairs(smem, SW2_HI, r, k, b.x, b.y, b.z, b.w, SW2_LO);
        }
    }
    if (tid == 0) s_tile = atomicAdd(&g_tile_counter, 1);
    __syncthreads();

    const int n_tiles = (N_NODES + 63) / 64;   // 782

    int tile = s_tile;
    while (tile < n_tiles) {
        int n0 = tile * 64;

        // ---- stage both branches ----
        {
            int r  = tid >> 3;
            int c0 = (tid & 7) * 16;
            int g  = n0 + r;
            const float4* hp = (const float4*)(nfeat + (size_t)g * D + c0);
            const float4* np = (const float4*)(hn    + (size_t)g * D + c0);
            #pragma unroll
            for (int i = 0; i < 4; i++) {
                float4 av = make_float4(0.f, 0.f, 0.f, 0.f);
                float4 mv = av;
                if (g < N_NODES) {
                    float4 hv = __ldg(hp + i);
                    float4 nv = __ldg(np + i);
                    av = make_float4(hv.x + nv.x, hv.y + nv.y, hv.z + nv.z, hv.w + nv.w);
                    mv = make_float4(hv.x * nv.x, hv.y * nv.y, hv.z * nv.z, hv.w * nv.w);
                }
                int k = c0 + i * 4;
                stA(smem, SADD_HI, SADD_LO, r, k, av);
                stA(smem, SMUL_HI, SMUL_LO, r, k, mv);
            }
        }
        __syncthreads();

        // prefetch next tile id while MMAs run
        if (tid == 0) s_tile = atomicAdd(&g_tile_counter, 1);

        float acc[2][2][2][4];   // [branch][mi][ni][frag]
        #pragma unroll
        for (int b = 0; b < 2; b++)
            #pragma unroll
            for (int mi = 0; mi < 2; mi++)
                #pragma unroll
                for (int ni = 0; ni < 2; ni++)
                    #pragma unroll
                    for (int f = 0; f < 4; f++) acc[b][mi][ni][f] = 0.f;

        #pragma unroll
        for (int branch = 0; branch < 2; branch++) {
            uint32_t ahi = sb + (branch ? SMUL_HI : SADD_HI);
            uint32_t alo = sb + (branch ? SMUL_LO : SADD_LO);
            uint32_t bhi = sb + (branch ? SW2_HI : SW1_HI);
            uint32_t blo = sb + (branch ? SW2_LO : SW1_LO);
            float*   accb = &acc[branch][0][0][0];

            #pragma unroll
            for (int kk = 0; kk < 8; kk++) {
                int kb2 = kk * 32;
                unsigned afr[2][4];
                ldsm4(afr[0], ahi + a_off + kb2);
                ldsm4(afr[1], ahi + a_off + 16 * (PAD * 2) + kb2);
                unsigned bh[4], bl[4];
                ldsm4(bh, bhi + b_off + kb2);
                ldsm4(bl, blo + b_off + kb2);
                #pragma unroll
                for (int mi = 0; mi < 2; mi++)
                    #pragma unroll
                    for (int ni = 0; ni < 2; ni++) {
                        float* c = accb + (mi * 2 + ni) * 4;
                        mma16816(c, afr[mi], bh + ni * 2);
                        mma16816(c, afr[mi], bl + ni * 2);
                    }
            }
            #pragma unroll
            for (int kk = 0; kk < 8; kk++) {
                int kb2 = kk * 32;
                unsigned afr[2][4];
                ldsm4(afr[0], alo + a_off + kb2);
                ldsm4(afr[1], alo + a_off + 16 * (PAD * 2) + kb2);
                unsigned bh[4];
                ldsm4(bh, bhi + b_off + kb2);
                #pragma unroll
                for (int mi = 0; mi < 2; mi++)
                    #pragma unroll
                    for (int ni = 0; ni < 2; ni++)
                        mma16816(accb + (mi * 2 + ni) * 4, afr[mi], bh + ni * 2);
            }
        }

        // ---- epilogue ----
        #pragma unroll
        for (int mi = 0; mi < 2; mi++) {
            int r_lo = n0 + warp_r * 32 + mi * 16 + g8;
            int r_hi = r_lo + 8;
            #pragma unroll
            for (int ni = 0; ni < 2; ni++) {
                int c0 = warp_c * 16 + ni * 8 + t4 * 2;
                if (r_lo < N_NODES) {
                    float2 o;
                    o.x = lrelu(acc[0][mi][ni][0]) + lrelu(acc[1][mi][ni][0]);
                    o.y = lrelu(acc[0][mi][ni][1]) + lrelu(acc[1][mi][ni][1]);
                    *(float2*)(out + (size_t)r_lo * D + c0) = o;
                }
                if (r_hi < N_NODES) {
                    float2 o;
                    o.x = lrelu(acc[0][mi][ni][2]) + lrelu(acc[1][mi][ni][2]);
                    o.y = lrelu(acc[0][mi][ni][3]) + lrelu(acc[1][mi][ni][3]);
                    *(float2*)(out + (size_t)r_hi * D + c0) = o;
                }
            }
        }
        __syncthreads();     // A buffers free; s_tile update visible
        tile = s_tile;
    }
}

// ---------------- launch ----------------
extern "C" void kernel_launch(void* const* d_in, const int* in_sizes, int n_in,
                              void* d_out, int out_size) {
    const float* nfeat = (const float*)d_in[0];
    const float* w     = (const float*)d_in[1];
    const float* W1    = (const float*)d_in[2];
    const float* W2    = (const float*)d_in[3];
    const void*  src   = d_in[4];
    const void*  dst   = d_in[5];

    float* outbuf = (float*)d_out;
    float* hn     = outbuf;                           // h_neighbor
    float* out2   = outbuf + (size_t)N_NODES * D;     // out

    count_kernel<<<(N_EDGES + 255) / 256, 256>>>(dst);
    scan_lookback_kernel<<<SCAN_NBLK, 256>>>();
    scatter_kernel<<<(N_EDGES + 255) / 256, 256>>>(src, dst, w);
    aggregate_kernel<<<(N_NODES * 32 + 255) / 256, 256>>>(nfeat, hn);

    cudaFuncSetAttribute(mma_gemm_kernel,
                         cudaFuncAttributeMaxDynamicSharedMemorySize, SM_TOTAL);
    mma_gemm_kernel<<<148, 512, SM_TOTAL>>>(nfeat, W1, W2, hn, out2);
}